// round 5
// baseline (speedup 1.0000x reference)
#include <cuda_runtime.h>
#include <cuda_bf16.h>

#define MAX_NODES 100000
#define DIM 64
#define KH 64               // half of concat-K
#define LN_EPS 1e-5f
#define NPB 128             // nodes per GEMM block
#define SSTR 68             // sIn row stride (floats): 68 mod 32 = 4 -> conflict-free a-loads
#define SMEM_FLOATS (KH * 64 + NPB * SSTR)   // 4096 + 8704 = 12800 -> 51200 B

// Scratch (no cudaMalloc allowed)
__device__ float g_agg[MAX_NODES * DIM];
__device__ float g_h1[MAX_NODES * DIM];
__device__ float g_deg[MAX_NODES];
__device__ unsigned g_is64;

// ---------------------------------------------------------------------------
// Detect int64 vs int32 edge_index (JAX x64-off silently downcasts).
// ---------------------------------------------------------------------------
__global__ void detect_dtype_kernel(const unsigned* __restrict__ ei_raw) {
    __shared__ unsigned s_any;
    if (threadIdx.x == 0) s_any = 0u;
    __syncthreads();
    unsigned v = 0;
    for (int i = 2 * threadIdx.x + 1; i < 2048; i += 2 * blockDim.x)
        v |= ei_raw[i];
    if (v) atomicOr(&s_any, 1u);
    __syncthreads();
    if (threadIdx.x == 0) g_is64 = (s_any == 0u) ? 1u : 0u;
}

// ---------------------------------------------------------------------------
// Zero agg + deg (float4-vectorized).
// ---------------------------------------------------------------------------
__global__ void zero_kernel(int n_nodes) {
    int i = blockIdx.x * blockDim.x + threadIdx.x;
    int agg4 = n_nodes * (DIM / 4);
    float4 z = make_float4(0.f, 0.f, 0.f, 0.f);
    if (i < agg4) ((float4*)g_agg)[i] = z;
    if (i < n_nodes / 4) ((float4*)g_deg)[i] = z;
    if (i == 0) {   // tail of deg if n_nodes not /4
        for (int t = (n_nodes / 4) * 4; t < n_nodes; t++) g_deg[t] = 0.0f;
    }
}

// ---------------------------------------------------------------------------
// sW layout helper: permuted so the two LDS.128 W-fetches per (k, o_group)
// hit 8 distinct bank-quads. Position of output o within a k-row:
//   og = o>>3, j = o&7 ->  j<4 : og*4+j   |   j>=4 : 32 + og*4 + (j-4)
// GEMM then reads: w0 = sW4[k*16 + og]  (outputs og*8+0..3)
//                  w1 = sW4[k*16 + 8 + og] (outputs og*8+4..7)
// ---------------------------------------------------------------------------
__device__ __forceinline__ int w_pos(int o) {
    int og = o >> 3, j = o & 7;
    return (j < 4) ? (og * 4 + j) : (32 + og * 4 + (j - 4));
}

// ---------------------------------------------------------------------------
// Kernel A: heterogeneous blocks.
//   blocks [0, n_sc_blocks)            : edge scatter (8 threads/edge, RED.v4)
//   blocks [n_sc_blocks, +n_gemm)      : GEMM1  h1 = b + x @ W1^T  (K=64)
// Scatter blocks are long/latency-bound; GEMM1 blocks fill SM compute slack.
// ---------------------------------------------------------------------------
__global__ void fused_A_kernel(const float* __restrict__ x,
                               const float* __restrict__ W,
                               const float* __restrict__ b,
                               const void* __restrict__ ei,
                               int n_nodes, int n_edges, int n_sc_blocks) {
    extern __shared__ float smem[];
    int tid = threadIdx.x;

    if ((int)blockIdx.x < n_sc_blocks) {
        // ---------------- scatter ----------------
        long long idx = (long long)blockIdx.x * 256 + tid;
        long long e = idx >> 3;
        int lane = (int)(idx & 7);
        if (e >= n_edges) return;

        long long dst, src;
        if (g_is64) {
            const long long* e64 = (const long long*)ei;
            dst = e64[e];
            src = e64[n_edges + e];
        } else {
            const int* e32 = (const int*)ei;
            dst = e32[e];
            src = e32[n_edges + e];
        }

        const float4* xs = (const float4*)(x + src * DIM);
        float* ag = g_agg + dst * DIM;
#pragma unroll
        for (int q = 0; q < 2; q++) {
            int c = lane * 2 + q;
            float4 v = xs[c];
            asm volatile(
                "red.global.add.v4.f32 [%0], {%1,%2,%3,%4};"
                :: "l"(ag + c * 4), "f"(v.x), "f"(v.y), "f"(v.z), "f"(v.w)
                : "memory");
        }
        if (lane == 0) atomicAdd(&g_deg[dst], 1.0f);
        return;
    }

    // ---------------- GEMM1: h1 = b + x @ W1^T ----------------
    float* sW  = smem;             // [64][64] permuted
    float* sIn = smem + KH * 64;   // [NPB][SSTR]
    int base = (blockIdx.x - n_sc_blocks) * NPB;

    for (int i = tid; i < 64 * KH; i += 256) {
        int o = i >> 6;            // output dim
        int k = i & 63;            // k within first half
        sW[k * 64 + w_pos(o)] = W[o * 128 + k];
    }
    for (int i = tid; i < NPB * 16; i += 256) {
        int n = i >> 4, c = i & 15;
        int node = base + n;
        float4 v = make_float4(0.f, 0.f, 0.f, 0.f);
        if (node < n_nodes)
            v = ((const float4*)(x + (long long)node * DIM))[c];
        *((float4*)(sIn + n * SSTR + c * 4)) = v;
    }
    __syncthreads();

    int lane = tid & 31, wid = tid >> 5;
    int ng = lane & 3, og = lane >> 2;
    const float* in0 = sIn + (wid * 16 + ng) * SSTR;
    const float4* sW4 = (const float4*)sW;

    float acc[4][8];
#pragma unroll
    for (int n = 0; n < 4; n++)
#pragma unroll
        for (int j = 0; j < 8; j++) acc[n][j] = 0.0f;

#pragma unroll 4
    for (int k = 0; k < KH; k++) {
        float4 w0 = sW4[k * 16 + og];
        float4 w1 = sW4[k * 16 + 8 + og];
        float av[4];
#pragma unroll
        for (int n = 0; n < 4; n++) av[n] = in0[n * 4 * SSTR + k];
#pragma unroll
        for (int n = 0; n < 4; n++) {
            acc[n][0] = fmaf(av[n], w0.x, acc[n][0]);
            acc[n][1] = fmaf(av[n], w0.y, acc[n][1]);
            acc[n][2] = fmaf(av[n], w0.z, acc[n][2]);
            acc[n][3] = fmaf(av[n], w0.w, acc[n][3]);
            acc[n][4] = fmaf(av[n], w1.x, acc[n][4]);
            acc[n][5] = fmaf(av[n], w1.y, acc[n][5]);
            acc[n][6] = fmaf(av[n], w1.z, acc[n][6]);
            acc[n][7] = fmaf(av[n], w1.w, acc[n][7]);
        }
    }

    float bb[8];
#pragma unroll
    for (int j = 0; j < 8; j++) bb[j] = b[og * 8 + j];

#pragma unroll
    for (int n = 0; n < 4; n++) {
        int node = base + wid * 16 + ng + 4 * n;
        if (node < n_nodes) {
            float4 v0, v1;
            v0.x = acc[n][0] + bb[0]; v0.y = acc[n][1] + bb[1];
            v0.z = acc[n][2] + bb[2]; v0.w = acc[n][3] + bb[3];
            v1.x = acc[n][4] + bb[4]; v1.y = acc[n][5] + bb[5];
            v1.z = acc[n][6] + bb[6]; v1.w = acc[n][7] + bb[7];
            float4* hp = (float4*)(g_h1 + (long long)node * DIM + og * 8);
            hp[0] = v0;
            hp[1] = v1;
        }
    }
}

// ---------------------------------------------------------------------------
// Kernel B: h = h1 + (agg/deg) @ W2^T ; ReLU ; LayerNorm ; out.
// ---------------------------------------------------------------------------
__global__ void compute_B_kernel(const float* __restrict__ W,
                                 const float* __restrict__ gamma,
                                 const float* __restrict__ beta,
                                 float* __restrict__ out,
                                 int n_nodes) {
    extern __shared__ float smem[];
    float* sW  = smem;             // [64][64] permuted (W2 half)
    float* sIn = smem + KH * 64;   // [NPB][SSTR]
    int tid = threadIdx.x;
    int base = blockIdx.x * NPB;

    for (int i = tid; i < 64 * KH; i += 256) {
        int o = i >> 6;
        int k = i & 63;
        sW[k * 64 + w_pos(o)] = W[o * 128 + KH + k];
    }
    for (int i = tid; i < NPB * 16; i += 256) {
        int n = i >> 4, c = i & 15;
        int node = base + n;
        float4 v = make_float4(0.f, 0.f, 0.f, 0.f);
        if (node < n_nodes) {
            v = ((const float4*)(g_agg + (long long)node * DIM))[c];
            float inv = 1.0f / fmaxf(g_deg[node], 1.0f);
            v.x *= inv; v.y *= inv; v.z *= inv; v.w *= inv;
        }
        *((float4*)(sIn + n * SSTR + c * 4)) = v;
    }
    __syncthreads();

    int lane = tid & 31, wid = tid >> 5;
    int ng = lane & 3, og = lane >> 2;
    const float* in0 = sIn + (wid * 16 + ng) * SSTR;
    const float4* sW4 = (const float4*)sW;

    float acc[4][8];
#pragma unroll
    for (int n = 0; n < 4; n++)
#pragma unroll
        for (int j = 0; j < 8; j++) acc[n][j] = 0.0f;

#pragma unroll 4
    for (int k = 0; k < KH; k++) {
        float4 w0 = sW4[k * 16 + og];
        float4 w1 = sW4[k * 16 + 8 + og];
        float av[4];
#pragma unroll
        for (int n = 0; n < 4; n++) av[n] = in0[n * 4 * SSTR + k];
#pragma unroll
        for (int n = 0; n < 4; n++) {
            acc[n][0] = fmaf(av[n], w0.x, acc[n][0]);
            acc[n][1] = fmaf(av[n], w0.y, acc[n][1]);
            acc[n][2] = fmaf(av[n], w0.z, acc[n][2]);
            acc[n][3] = fmaf(av[n], w0.w, acc[n][3]);
            acc[n][4] = fmaf(av[n], w1.x, acc[n][4]);
            acc[n][5] = fmaf(av[n], w1.y, acc[n][5]);
            acc[n][6] = fmaf(av[n], w1.z, acc[n][6]);
            acc[n][7] = fmaf(av[n], w1.w, acc[n][7]);
        }
    }

    float gg[8], be[8];
#pragma unroll
    for (int j = 0; j < 8; j++) {
        gg[j] = gamma[og * 8 + j];
        be[j] = beta[og * 8 + j];
    }

#pragma unroll
    for (int n = 0; n < 4; n++) {
        int node = base + wid * 16 + ng + 4 * n;
        float h[8];
        if (node < n_nodes) {
            const float4* hp = (const float4*)(g_h1 + (long long)node * DIM + og * 8);
            float4 h0 = hp[0], h1v = hp[1];
            h[0] = h0.x; h[1] = h0.y; h[2] = h0.z; h[3] = h0.w;
            h[4] = h1v.x; h[5] = h1v.y; h[6] = h1v.z; h[7] = h1v.w;
        } else {
#pragma unroll
            for (int j = 0; j < 8; j++) h[j] = 0.0f;
        }

        float s = 0.0f, s2 = 0.0f;
#pragma unroll
        for (int j = 0; j < 8; j++) {
            float v = fmaxf(h[j] + acc[n][j], 0.0f);
            h[j] = v;
            s += v;
            s2 = fmaf(v, v, s2);
        }
#pragma unroll
        for (int m = 4; m <= 16; m <<= 1) {
            s  += __shfl_xor_sync(0xFFFFFFFFu, s,  m);
            s2 += __shfl_xor_sync(0xFFFFFFFFu, s2, m);
        }
        float mu  = s * (1.0f / 64.0f);
        float var = s2 * (1.0f / 64.0f) - mu * mu;
        float rstd = rsqrtf(var + LN_EPS);

        if (node < n_nodes) {
            float4 v0, v1;
            v0.x = (h[0] - mu) * rstd * gg[0] + be[0];
            v0.y = (h[1] - mu) * rstd * gg[1] + be[1];
            v0.z = (h[2] - mu) * rstd * gg[2] + be[2];
            v0.w = (h[3] - mu) * rstd * gg[3] + be[3];
            v1.x = (h[4] - mu) * rstd * gg[4] + be[4];
            v1.y = (h[5] - mu) * rstd * gg[5] + be[5];
            v1.z = (h[6] - mu) * rstd * gg[6] + be[6];
            v1.w = (h[7] - mu) * rstd * gg[7] + be[7];
            float4* op = (float4*)(out + (long long)node * DIM + og * 8);
            op[0] = v0;
            op[1] = v1;
        }
    }
}

// ---------------------------------------------------------------------------
extern "C" void kernel_launch(void* const* d_in, const int* in_sizes, int n_in,
                              void* d_out, int out_size) {
    const float* x     = (const float*)d_in[0];   // [N, 64]
    const float* W     = (const float*)d_in[1];   // [64, 128]
    const float* b     = (const float*)d_in[2];   // [64]
    const float* gamma = (const float*)d_in[3];   // [64]
    const float* beta  = (const float*)d_in[4];   // [64]
    const void*  ei    = d_in[5];                 // [2, E] int32 or int64

    int n_nodes = in_sizes[0] / DIM;
    int n_edges = in_sizes[5] / 2;
    float* out = (float*)d_out;

    detect_dtype_kernel<<<1, 256>>>((const unsigned*)ei);

    int zero4 = n_nodes * (DIM / 4);
    zero_kernel<<<(zero4 + 255) / 256, 256>>>(n_nodes);

    int smem_bytes = SMEM_FLOATS * sizeof(float);   // 51200 B
    static bool attr_set = false;
    cudaFuncSetAttribute(fused_A_kernel,
                         cudaFuncAttributeMaxDynamicSharedMemorySize, smem_bytes);
    cudaFuncSetAttribute(compute_B_kernel,
                         cudaFuncAttributeMaxDynamicSharedMemorySize, smem_bytes);
    (void)attr_set;

    long long sc_threads = (long long)n_edges * 8;
    int n_sc_blocks = (int)((sc_threads + 255) / 256);
    int n_gemm_blocks = (n_nodes + NPB - 1) / NPB;

    fused_A_kernel<<<n_sc_blocks + n_gemm_blocks, 256, smem_bytes>>>(
        x, W, b, ei, n_nodes, n_edges, n_sc_blocks);

    compute_B_kernel<<<n_gemm_blocks, 256, smem_bytes>>>(
        W, gamma, beta, out, n_nodes);
}

// round 7
// speedup vs baseline: 1.3283x; 1.3283x over previous
#include <cuda_runtime.h>
#include <cuda_bf16.h>

#define MAX_NODES 100000
#define DIM 64
#define KH 64               // half of concat-K
#define LN_EPS 1e-5f
#define NPB 64              // nodes per GEMM tile/block
#define SSTR 68             // sIn row stride (floats): conflict-free a-loads
#define SMEM_FLTS (KH * 64 + NPB * SSTR)   // 4096 + 4352 = 8448 floats = 33792 B

// Scratch (no cudaMalloc allowed)
__device__ float g_agg[MAX_NODES * DIM];
__device__ float g_h1[MAX_NODES * DIM];
__device__ float g_deg[MAX_NODES];
__device__ float g_Wt1[KH * 64];   // W[:, :64]  transposed+permuted
__device__ float g_Wt2[KH * 64];   // W[:, 64:]  transposed+permuted
__device__ unsigned g_is64;

// Permuted column position so the two LDS.128 W-fetches per (k, og) are
// contiguous 128B: j<4 -> og*4+j ; j>=4 -> 32 + og*4 + (j-4)
__device__ __forceinline__ int w_pos(int o) {
    int og = o >> 3, j = o & 7;
    return (j < 4) ? (og * 4 + j) : (32 + og * 4 + (j - 4));
}

// ---------------------------------------------------------------------------
// Detect int64 vs int32 edge_index (JAX x64-off silently downcasts).
// ---------------------------------------------------------------------------
__global__ void detect_dtype_kernel(const unsigned* __restrict__ ei_raw) {
    __shared__ unsigned s_any;
    if (threadIdx.x == 0) s_any = 0u;
    __syncthreads();
    unsigned v = 0;
    for (int i = 2 * threadIdx.x + 1; i < 2048; i += 2 * blockDim.x)
        v |= ei_raw[i];
    if (v) atomicOr(&s_any, 1u);
    __syncthreads();
    if (threadIdx.x == 0) g_is64 = (s_any == 0u) ? 1u : 0u;
}

// ---------------------------------------------------------------------------
// One-time (per launch) W transpose into permuted k-major halves.
// ---------------------------------------------------------------------------
__global__ void prep_kernel(const float* __restrict__ W) {
    int i = blockIdx.x * blockDim.x + threadIdx.x;
    if (i < 64 * 128) {
        int o = i >> 7;            // output dim
        int k = i & 127;           // concat-k
        float v = W[i];
        if (k < KH) g_Wt1[k * 64 + w_pos(o)] = v;
        else        g_Wt2[(k - KH) * 64 + w_pos(o)] = v;
    }
}

// ---------------------------------------------------------------------------
// Zero agg + deg (float4-vectorized).
// ---------------------------------------------------------------------------
__global__ void zero_kernel(int n_nodes) {
    int i = blockIdx.x * blockDim.x + threadIdx.x;
    int agg4 = n_nodes * (DIM / 4);
    float4 z = make_float4(0.f, 0.f, 0.f, 0.f);
    if (i < agg4) ((float4*)g_agg)[i] = z;
    if (i < n_nodes / 4) ((float4*)g_deg)[i] = z;
    if (i == 0) {
        for (int t = (n_nodes / 4) * 4; t < n_nodes; t++) g_deg[t] = 0.0f;
    }
}

// ---------------------------------------------------------------------------
// Phase A: warp-heterogeneous block.
//   warps 0-3  : GEMM1  h1 = b + x @ W1^T  for NPB=64 nodes (tile 4n x 8o)
//   warps 4-7  : edge scatter slice (8 thr/edge, RED.v4, 2-edge pipeline)
// GEMM work (~30us chip-wide) hides under the L2-bound scatter (~75us).
// ---------------------------------------------------------------------------
__global__ void phaseA_kernel(const float* __restrict__ x,
                              const float* __restrict__ b,
                              const void* __restrict__ ei,
                              int n_nodes, int n_edges, int epb) {
    extern __shared__ float smem[];
    float* sW  = smem;              // [64][64] permuted
    float* sIn = smem + KH * 64;    // [NPB][SSTR]
    int tid = threadIdx.x;

    if (tid < 128) {
        // ---------------- GEMM1 half ----------------
        int base = blockIdx.x * NPB;

        for (int i = tid; i < (KH * 64) / 4; i += 128)
            ((float4*)sW)[i] = ((const float4*)g_Wt1)[i];

        for (int i = tid; i < NPB * 16; i += 128) {
            int n = i >> 4, c = i & 15;
            int node = base + n;
            float4 v = make_float4(0.f, 0.f, 0.f, 0.f);
            if (node < n_nodes)
                v = ((const float4*)(x + (size_t)node * DIM))[c];
            *((float4*)(sIn + n * SSTR + c * 4)) = v;
        }
        asm volatile("bar.sync 1, 128;" ::: "memory");

        int lane = tid & 31, wid = tid >> 5;       // wid 0..3
        int ng = lane & 3, og = lane >> 2;
        const float* in0 = sIn + (wid * 16 + ng) * SSTR;
        const float4* sW4 = (const float4*)sW;

        float acc[4][8];
#pragma unroll
        for (int n = 0; n < 4; n++)
#pragma unroll
            for (int j = 0; j < 8; j++) acc[n][j] = 0.0f;

#pragma unroll 4
        for (int k = 0; k < KH; k++) {
            float4 w0 = sW4[k * 16 + og];
            float4 w1 = sW4[k * 16 + 8 + og];
            float av[4];
#pragma unroll
            for (int n = 0; n < 4; n++) av[n] = in0[n * 4 * SSTR + k];
#pragma unroll
            for (int n = 0; n < 4; n++) {
                acc[n][0] = fmaf(av[n], w0.x, acc[n][0]);
                acc[n][1] = fmaf(av[n], w0.y, acc[n][1]);
                acc[n][2] = fmaf(av[n], w0.z, acc[n][2]);
                acc[n][3] = fmaf(av[n], w0.w, acc[n][3]);
                acc[n][4] = fmaf(av[n], w1.x, acc[n][4]);
                acc[n][5] = fmaf(av[n], w1.y, acc[n][5]);
                acc[n][6] = fmaf(av[n], w1.z, acc[n][6]);
                acc[n][7] = fmaf(av[n], w1.w, acc[n][7]);
            }
        }

        float bb[8];
#pragma unroll
        for (int j = 0; j < 8; j++) bb[j] = b[og * 8 + j];

#pragma unroll
        for (int n = 0; n < 4; n++) {
            int node = base + wid * 16 + ng + 4 * n;
            if (node < n_nodes) {
                float4 v0, v1;
                v0.x = acc[n][0] + bb[0]; v0.y = acc[n][1] + bb[1];
                v0.z = acc[n][2] + bb[2]; v0.w = acc[n][3] + bb[3];
                v1.x = acc[n][4] + bb[4]; v1.y = acc[n][5] + bb[5];
                v1.z = acc[n][6] + bb[6]; v1.w = acc[n][7] + bb[7];
                float4* hp = (float4*)(g_h1 + (size_t)node * DIM + og * 8);
                hp[0] = v0;
                hp[1] = v1;
            }
        }
    } else {
        // ---------------- scatter half ----------------
        int t = tid - 128;
        int lane = t & 7;
        int sub = t >> 3;                         // 0..15
        long long e0 = (long long)blockIdx.x * epb;
        long long e1 = e0 + epb;
        if (e1 > n_edges) e1 = n_edges;
        if (e0 >= e1) return;
        bool is64 = (g_is64 != 0u);
        const long long* e64 = (const long long*)ei;
        const int* e32 = (const int*)ei;
        int c0 = lane * 2, c1 = lane * 2 + 1;

        long long e = e0 + sub;
        // 2-edge software pipeline for MLP
        for (; e + 16 < e1; e += 32) {
            long long dA, sA, dB, sB;
            long long eB = e + 16;
            if (is64) {
                dA = e64[e];  sA = e64[n_edges + e];
                dB = e64[eB]; sB = e64[n_edges + eB];
            } else {
                dA = e32[e];  sA = e32[n_edges + e];
                dB = e32[eB]; sB = e32[n_edges + eB];
            }
            const float4* xsA = (const float4*)(x + sA * DIM);
            const float4* xsB = (const float4*)(x + sB * DIM);
            float4 a0 = xsA[c0], a1 = xsA[c1];
            float4 b0 = xsB[c0], b1 = xsB[c1];
            float* agA = g_agg + dA * DIM;
            float* agB = g_agg + dB * DIM;
            asm volatile("red.global.add.v4.f32 [%0], {%1,%2,%3,%4};"
                :: "l"(agA + c0 * 4), "f"(a0.x), "f"(a0.y), "f"(a0.z), "f"(a0.w) : "memory");
            asm volatile("red.global.add.v4.f32 [%0], {%1,%2,%3,%4};"
                :: "l"(agA + c1 * 4), "f"(a1.x), "f"(a1.y), "f"(a1.z), "f"(a1.w) : "memory");
            asm volatile("red.global.add.v4.f32 [%0], {%1,%2,%3,%4};"
                :: "l"(agB + c0 * 4), "f"(b0.x), "f"(b0.y), "f"(b0.z), "f"(b0.w) : "memory");
            asm volatile("red.global.add.v4.f32 [%0], {%1,%2,%3,%4};"
                :: "l"(agB + c1 * 4), "f"(b1.x), "f"(b1.y), "f"(b1.z), "f"(b1.w) : "memory");
            if (lane == 0) {
                atomicAdd(&g_deg[dA], 1.0f);
                atomicAdd(&g_deg[dB], 1.0f);
            }
        }
        for (; e < e1; e += 16) {
            long long dst, src;
            if (is64) { dst = e64[e]; src = e64[n_edges + e]; }
            else      { dst = e32[e]; src = e32[n_edges + e]; }
            const float4* xs = (const float4*)(x + src * DIM);
            float4 v0 = xs[c0], v1 = xs[c1];
            float* ag = g_agg + dst * DIM;
            asm volatile("red.global.add.v4.f32 [%0], {%1,%2,%3,%4};"
                :: "l"(ag + c0 * 4), "f"(v0.x), "f"(v0.y), "f"(v0.z), "f"(v0.w) : "memory");
            asm volatile("red.global.add.v4.f32 [%0], {%1,%2,%3,%4};"
                :: "l"(ag + c1 * 4), "f"(v1.x), "f"(v1.y), "f"(v1.z), "f"(v1.w) : "memory");
            if (lane == 0) atomicAdd(&g_deg[dst], 1.0f);
        }
    }
}

// ---------------------------------------------------------------------------
// Phase B: h = h1 + (agg/deg) @ W2^T ; ReLU ; LayerNorm ; out.
// NPB=64, 8 warps, lane tile 2 nodes x 8 outputs.
// ---------------------------------------------------------------------------
__global__ void phaseB_kernel(const float* __restrict__ gamma,
                              const float* __restrict__ beta,
                              float* __restrict__ out,
                              int n_nodes) {
    extern __shared__ float smem[];
    float* sW  = smem;              // [64][64] permuted (W2)
    float* sIn = smem + KH * 64;    // [NPB][SSTR]
    int tid = threadIdx.x;
    int base = blockIdx.x * NPB;

    for (int i = tid; i < (KH * 64) / 4; i += 256)
        ((float4*)sW)[i] = ((const float4*)g_Wt2)[i];

    for (int i = tid; i < NPB * 16; i += 256) {
        int n = i >> 4, c = i & 15;
        int node = base + n;
        float4 v = make_float4(0.f, 0.f, 0.f, 0.f);
        if (node < n_nodes) {
            v = ((const float4*)(g_agg + (size_t)node * DIM))[c];
            float inv = 1.0f / fmaxf(g_deg[node], 1.0f);
            v.x *= inv; v.y *= inv; v.z *= inv; v.w *= inv;
        }
        *((float4*)(sIn + n * SSTR + c * 4)) = v;
    }
    __syncthreads();

    int lane = tid & 31, wid = tid >> 5;          // 8 warps, 8 nodes each
    int ng = lane & 3, og = lane >> 2;
    const float* in0 = sIn + (wid * 8 + ng) * SSTR;
    const float4* sW4 = (const float4*)sW;

    float acc[2][8];
#pragma unroll
    for (int n = 0; n < 2; n++)
#pragma unroll
        for (int j = 0; j < 8; j++) acc[n][j] = 0.0f;

#pragma unroll 4
    for (int k = 0; k < KH; k++) {
        float4 w0 = sW4[k * 16 + og];
        float4 w1 = sW4[k * 16 + 8 + og];
        float av0 = in0[k];
        float av1 = in0[4 * SSTR + k];
        acc[0][0] = fmaf(av0, w0.x, acc[0][0]);
        acc[0][1] = fmaf(av0, w0.y, acc[0][1]);
        acc[0][2] = fmaf(av0, w0.z, acc[0][2]);
        acc[0][3] = fmaf(av0, w0.w, acc[0][3]);
        acc[0][4] = fmaf(av0, w1.x, acc[0][4]);
        acc[0][5] = fmaf(av0, w1.y, acc[0][5]);
        acc[0][6] = fmaf(av0, w1.z, acc[0][6]);
        acc[0][7] = fmaf(av0, w1.w, acc[0][7]);
        acc[1][0] = fmaf(av1, w0.x, acc[1][0]);
        acc[1][1] = fmaf(av1, w0.y, acc[1][1]);
        acc[1][2] = fmaf(av1, w0.z, acc[1][2]);
        acc[1][3] = fmaf(av1, w0.w, acc[1][3]);
        acc[1][4] = fmaf(av1, w1.x, acc[1][4]);
        acc[1][5] = fmaf(av1, w1.y, acc[1][5]);
        acc[1][6] = fmaf(av1, w1.z, acc[1][6]);
        acc[1][7] = fmaf(av1, w1.w, acc[1][7]);
    }

    float gg[8], be[8];
#pragma unroll
    for (int j = 0; j < 8; j++) {
        gg[j] = gamma[og * 8 + j];
        be[j] = beta[og * 8 + j];
    }

#pragma unroll
    for (int n = 0; n < 2; n++) {
        int node = base + wid * 8 + ng + 4 * n;
        float h[8];
        if (node < n_nodes) {
            const float4* hp = (const float4*)(g_h1 + (size_t)node * DIM + og * 8);
            float4 h0 = hp[0], h1v = hp[1];
            h[0] = h0.x; h[1] = h0.y; h[2] = h0.z; h[3] = h0.w;
            h[4] = h1v.x; h[5] = h1v.y; h[6] = h1v.z; h[7] = h1v.w;
        } else {
#pragma unroll
            for (int j = 0; j < 8; j++) h[j] = 0.0f;
        }

        float s = 0.0f, s2 = 0.0f;
#pragma unroll
        for (int j = 0; j < 8; j++) {
            float v = fmaxf(h[j] + acc[n][j], 0.0f);
            h[j] = v;
            s += v;
            s2 = fmaf(v, v, s2);
        }
#pragma unroll
        for (int m = 4; m <= 16; m <<= 1) {
            s  += __shfl_xor_sync(0xFFFFFFFFu, s,  m);
            s2 += __shfl_xor_sync(0xFFFFFFFFu, s2, m);
        }
        float mu  = s * (1.0f / 64.0f);
        float var = s2 * (1.0f / 64.0f) - mu * mu;
        float rstd = rsqrtf(var + LN_EPS);

        if (node < n_nodes) {
            float4 v0, v1;
            v0.x = (h[0] - mu) * rstd * gg[0] + be[0];
            v0.y = (h[1] - mu) * rstd * gg[1] + be[1];
            v0.z = (h[2] - mu) * rstd * gg[2] + be[2];
            v0.w = (h[3] - mu) * rstd * gg[3] + be[3];
            v1.x = (h[4] - mu) * rstd * gg[4] + be[4];
            v1.y = (h[5] - mu) * rstd * gg[5] + be[5];
            v1.z = (h[6] - mu) * rstd * gg[6] + be[6];
            v1.w = (h[7] - mu) * rstd * gg[7] + be[7];
            float4* op = (float4*)(out + (size_t)node * DIM + og * 8);
            op[0] = v0;
            op[1] = v1;
        }
    }
}

// ---------------------------------------------------------------------------
extern "C" void kernel_launch(void* const* d_in, const int* in_sizes, int n_in,
                              void* d_out, int out_size) {
    const float* x     = (const float*)d_in[0];   // [N, 64]
    const float* W     = (const float*)d_in[1];   // [64, 128]
    const float* b     = (const float*)d_in[2];   // [64]
    const float* gamma = (const float*)d_in[3];   // [64]
    const float* beta  = (const float*)d_in[4];   // [64]
    const void*  ei    = d_in[5];                 // [2, E] int32 or int64

    int n_nodes = in_sizes[0] / DIM;
    int n_edges = in_sizes[5] / 2;
    float* out = (float*)d_out;

    detect_dtype_kernel<<<1, 256>>>((const unsigned*)ei);
    prep_kernel<<<32, 256>>>(W);

    int zero4 = n_nodes * (DIM / 4);
    zero_kernel<<<(zero4 + 255) / 256, 256>>>(n_nodes);

    int n_blocks = (n_nodes + NPB - 1) / NPB;                 // 1563
    int epb = (n_edges + n_blocks - 1) / n_blocks;            // edges per block
    if (epb < 1) epb = 1;
    int smem_bytes = SMEM_FLTS * sizeof(float);               // 33792 B (< 48K default)

    phaseA_kernel<<<n_blocks, 256, smem_bytes>>>(x, b, ei, n_nodes, n_edges, epb);
    phaseB_kernel<<<n_blocks, 256, smem_bytes>>>(gamma, beta, out, n_nodes);
}

// round 8
// speedup vs baseline: 1.4561x; 1.0962x over previous
#include <cuda_runtime.h>
#include <cuda_bf16.h>

#define MAX_NODES 100000
#define DIM 64
#define KH 64               // half of concat-K
#define LN_EPS 1e-5f
#define NPB_A 32            // nodes per phaseA GEMM tile
#define NPB_B 64            // nodes per phaseB tile
#define SSTR 68             // sIn row stride (floats): conflict-free a-loads
#define SC_SUBS 24          // scatter sub-groups (6 warps * 32 / 8)
#define SMEM_A ((KH * 64 + NPB_A * SSTR))   // 4096+2176 = 6272 floats = 25088 B
#define SMEM_B ((KH * 64 + NPB_B * SSTR))   // 4096+4352 = 8448 floats = 33792 B

// Scratch (no cudaMalloc allowed)
__device__ float g_agg[MAX_NODES * DIM];
__device__ float g_h1[MAX_NODES * DIM];
__device__ float g_deg[MAX_NODES];
__device__ float g_Wt1[KH * 64];   // W[:, :64]  transposed+permuted
__device__ float g_Wt2[KH * 64];   // W[:, 64:]  transposed+permuted
__device__ unsigned g_is64;

// Permuted column position so the two LDS.128 W-fetches per (k, og) are
// contiguous 128B: j<4 -> og*4+j ; j>=4 -> 32 + og*4 + (j-4)
__device__ __forceinline__ int w_pos(int o) {
    int og = o >> 3, j = o & 7;
    return (j < 4) ? (og * 4 + j) : (32 + og * 4 + (j - 4));
}

// ---------------------------------------------------------------------------
// Fused init: zero agg/deg (whole grid), transpose W (first slices),
// detect edge dtype (block 0).
// ---------------------------------------------------------------------------
__global__ void init_kernel(const float* __restrict__ W,
                            const unsigned* __restrict__ ei_raw,
                            int n_nodes) {
    int gi = blockIdx.x * 256 + threadIdx.x;

    int agg4 = n_nodes * (DIM / 4);
    if (gi < agg4)
        ((float4*)g_agg)[gi] = make_float4(0.f, 0.f, 0.f, 0.f);
    if (gi < n_nodes) g_deg[gi] = 0.0f;

    if (gi < 64 * 128) {
        int o = gi >> 7;           // output dim
        int k = gi & 127;          // concat-k
        float v = W[gi];
        if (k < KH) g_Wt1[k * 64 + w_pos(o)] = v;
        else        g_Wt2[(k - KH) * 64 + w_pos(o)] = v;
    }

    if (blockIdx.x == 0) {
        __shared__ unsigned s_any;
        if (threadIdx.x == 0) s_any = 0u;
        __syncthreads();
        unsigned v = 0;
        for (int i = 2 * threadIdx.x + 1; i < 2048; i += 512)
            v |= ei_raw[i];
        if (v) atomicOr(&s_any, 1u);
        __syncthreads();
        if (threadIdx.x == 0) g_is64 = (s_any == 0u) ? 1u : 0u;
    }
}

// ---------------------------------------------------------------------------
// Phase A: warp-heterogeneous block, rebalanced for scatter concurrency.
//   warps 0-1  : GEMM1  h1 = b + x @ W1^T  for NPB_A=32 nodes (tile 4n x 8o)
//   warps 2-7  : edge scatter slice (8 thr/edge, RED.v4, 2-edge pipeline)
// launch_bounds(256,4): 64-reg cap -> 4 CTAs/SM -> 768 scatter threads/SM.
// ---------------------------------------------------------------------------
__global__ void __launch_bounds__(256, 4)
phaseA_kernel(const float* __restrict__ x,
              const float* __restrict__ b,
              const void* __restrict__ ei,
              int n_nodes, int n_edges, int epb) {
    extern __shared__ float smem[];
    float* sW  = smem;               // [64][64] permuted
    float* sIn = smem + KH * 64;     // [NPB_A][SSTR]
    int tid = threadIdx.x;

    if (tid < 64) {
        // ---------------- GEMM1 half (2 warps, 32 nodes) ----------------
        int base = blockIdx.x * NPB_A;

        for (int i = tid; i < (KH * 64) / 4; i += 64)
            ((float4*)sW)[i] = ((const float4*)g_Wt1)[i];

        for (int i = tid; i < NPB_A * 16; i += 64) {
            int n = i >> 4, c = i & 15;
            int node = base + n;
            float4 v = make_float4(0.f, 0.f, 0.f, 0.f);
            if (node < n_nodes)
                v = ((const float4*)(x + (size_t)node * DIM))[c];
            *((float4*)(sIn + n * SSTR + c * 4)) = v;
        }
        asm volatile("bar.sync 1, 64;" ::: "memory");

        int lane = tid & 31, wid = tid >> 5;        // wid 0..1
        int ng = lane & 3, og = lane >> 2;
        const float* in0 = sIn + (wid * 16 + ng) * SSTR;
        const float4* sW4 = (const float4*)sW;

        float acc[4][8];
#pragma unroll
        for (int n = 0; n < 4; n++)
#pragma unroll
            for (int j = 0; j < 8; j++) acc[n][j] = 0.0f;

#pragma unroll 4
        for (int k = 0; k < KH; k++) {
            float4 w0 = sW4[k * 16 + og];
            float4 w1 = sW4[k * 16 + 8 + og];
            float av[4];
#pragma unroll
            for (int n = 0; n < 4; n++) av[n] = in0[n * 4 * SSTR + k];
#pragma unroll
            for (int n = 0; n < 4; n++) {
                acc[n][0] = fmaf(av[n], w0.x, acc[n][0]);
                acc[n][1] = fmaf(av[n], w0.y, acc[n][1]);
                acc[n][2] = fmaf(av[n], w0.z, acc[n][2]);
                acc[n][3] = fmaf(av[n], w0.w, acc[n][3]);
                acc[n][4] = fmaf(av[n], w1.x, acc[n][4]);
                acc[n][5] = fmaf(av[n], w1.y, acc[n][5]);
                acc[n][6] = fmaf(av[n], w1.z, acc[n][6]);
                acc[n][7] = fmaf(av[n], w1.w, acc[n][7]);
            }
        }

        float bb[8];
#pragma unroll
        for (int j = 0; j < 8; j++) bb[j] = b[og * 8 + j];

#pragma unroll
        for (int n = 0; n < 4; n++) {
            int node = base + wid * 16 + ng + 4 * n;
            if (node < n_nodes) {
                float4 v0, v1;
                v0.x = acc[n][0] + bb[0]; v0.y = acc[n][1] + bb[1];
                v0.z = acc[n][2] + bb[2]; v0.w = acc[n][3] + bb[3];
                v1.x = acc[n][4] + bb[4]; v1.y = acc[n][5] + bb[5];
                v1.z = acc[n][6] + bb[6]; v1.w = acc[n][7] + bb[7];
                float4* hp = (float4*)(g_h1 + (size_t)node * DIM + og * 8);
                hp[0] = v0;
                hp[1] = v1;
            }
        }
    } else {
        // ---------------- scatter half (6 warps) ----------------
        int t = tid - 64;
        int lane = t & 7;
        int sub = t >> 3;                          // 0..23
        long long e0 = (long long)blockIdx.x * epb;
        long long e1 = e0 + epb;
        if (e1 > n_edges) e1 = n_edges;
        if (e0 >= e1) return;
        bool is64 = (g_is64 != 0u);
        const long long* e64 = (const long long*)ei;
        const int* e32 = (const int*)ei;
        int c0 = lane * 2, c1 = lane * 2 + 1;

        long long e = e0 + sub;
        // 2-edge software pipeline for MLP
        for (; e + SC_SUBS < e1; e += 2 * SC_SUBS) {
            long long dA, sA, dB, sB;
            long long eB = e + SC_SUBS;
            if (is64) {
                dA = e64[e];  sA = e64[n_edges + e];
                dB = e64[eB]; sB = e64[n_edges + eB];
            } else {
                dA = e32[e];  sA = e32[n_edges + e];
                dB = e32[eB]; sB = e32[n_edges + eB];
            }
            const float4* xsA = (const float4*)(x + sA * DIM);
            const float4* xsB = (const float4*)(x + sB * DIM);
            float4 a0 = xsA[c0], a1 = xsA[c1];
            float4 b0 = xsB[c0], b1 = xsB[c1];
            float* agA = g_agg + dA * DIM;
            float* agB = g_agg + dB * DIM;
            asm volatile("red.global.add.v4.f32 [%0], {%1,%2,%3,%4};"
                :: "l"(agA + c0 * 4), "f"(a0.x), "f"(a0.y), "f"(a0.z), "f"(a0.w) : "memory");
            asm volatile("red.global.add.v4.f32 [%0], {%1,%2,%3,%4};"
                :: "l"(agA + c1 * 4), "f"(a1.x), "f"(a1.y), "f"(a1.z), "f"(a1.w) : "memory");
            asm volatile("red.global.add.v4.f32 [%0], {%1,%2,%3,%4};"
                :: "l"(agB + c0 * 4), "f"(b0.x), "f"(b0.y), "f"(b0.z), "f"(b0.w) : "memory");
            asm volatile("red.global.add.v4.f32 [%0], {%1,%2,%3,%4};"
                :: "l"(agB + c1 * 4), "f"(b1.x), "f"(b1.y), "f"(b1.z), "f"(b1.w) : "memory");
            if (lane == 0) {
                atomicAdd(&g_deg[dA], 1.0f);
                atomicAdd(&g_deg[dB], 1.0f);
            }
        }
        for (; e < e1; e += SC_SUBS) {
            long long dst, src;
            if (is64) { dst = e64[e]; src = e64[n_edges + e]; }
            else      { dst = e32[e]; src = e32[n_edges + e]; }
            const float4* xs = (const float4*)(x + src * DIM);
            float4 v0 = xs[c0], v1 = xs[c1];
            float* ag = g_agg + dst * DIM;
            asm volatile("red.global.add.v4.f32 [%0], {%1,%2,%3,%4};"
                :: "l"(ag + c0 * 4), "f"(v0.x), "f"(v0.y), "f"(v0.z), "f"(v0.w) : "memory");
            asm volatile("red.global.add.v4.f32 [%0], {%1,%2,%3,%4};"
                :: "l"(ag + c1 * 4), "f"(v1.x), "f"(v1.y), "f"(v1.z), "f"(v1.w) : "memory");
            if (lane == 0) atomicAdd(&g_deg[dst], 1.0f);
        }
    }
}

// ---------------------------------------------------------------------------
// Phase B: h = h1 + (agg/deg) @ W2^T ; ReLU ; LayerNorm ; out.
// NPB_B=64, 8 warps, lane tile 2 nodes x 8 outputs.
// ---------------------------------------------------------------------------
__global__ void __launch_bounds__(256, 4)
phaseB_kernel(const float* __restrict__ gamma,
              const float* __restrict__ beta,
              float* __restrict__ out,
              int n_nodes) {
    extern __shared__ float smem[];
    float* sW  = smem;               // [64][64] permuted (W2)
    float* sIn = smem + KH * 64;     // [NPB_B][SSTR]
    int tid = threadIdx.x;
    int base = blockIdx.x * NPB_B;

    for (int i = tid; i < (KH * 64) / 4; i += 256)
        ((float4*)sW)[i] = ((const float4*)g_Wt2)[i];

    for (int i = tid; i < NPB_B * 16; i += 256) {
        int n = i >> 4, c = i & 15;
        int node = base + n;
        float4 v = make_float4(0.f, 0.f, 0.f, 0.f);
        if (node < n_nodes) {
            v = ((const float4*)(g_agg + (size_t)node * DIM))[c];
            float inv = 1.0f / fmaxf(g_deg[node], 1.0f);
            v.x *= inv; v.y *= inv; v.z *= inv; v.w *= inv;
        }
        *((float4*)(sIn + n * SSTR + c * 4)) = v;
    }
    __syncthreads();

    int lane = tid & 31, wid = tid >> 5;           // 8 warps, 8 nodes each
    int ng = lane & 3, og = lane >> 2;
    const float* in0 = sIn + (wid * 8 + ng) * SSTR;
    const float4* sW4 = (const float4*)sW;

    float acc[2][8];
#pragma unroll
    for (int n = 0; n < 2; n++)
#pragma unroll
        for (int j = 0; j < 8; j++) acc[n][j] = 0.0f;

#pragma unroll 4
    for (int k = 0; k < KH; k++) {
        float4 w0 = sW4[k * 16 + og];
        float4 w1 = sW4[k * 16 + 8 + og];
        float av0 = in0[k];
        float av1 = in0[4 * SSTR + k];
        acc[0][0] = fmaf(av0, w0.x, acc[0][0]);
        acc[0][1] = fmaf(av0, w0.y, acc[0][1]);
        acc[0][2] = fmaf(av0, w0.z, acc[0][2]);
        acc[0][3] = fmaf(av0, w0.w, acc[0][3]);
        acc[0][4] = fmaf(av0, w1.x, acc[0][4]);
        acc[0][5] = fmaf(av0, w1.y, acc[0][5]);
        acc[0][6] = fmaf(av0, w1.z, acc[0][6]);
        acc[0][7] = fmaf(av0, w1.w, acc[0][7]);
        acc[1][0] = fmaf(av1, w0.x, acc[1][0]);
        acc[1][1] = fmaf(av1, w0.y, acc[1][1]);
        acc[1][2] = fmaf(av1, w0.z, acc[1][2]);
        acc[1][3] = fmaf(av1, w0.w, acc[1][3]);
        acc[1][4] = fmaf(av1, w1.x, acc[1][4]);
        acc[1][5] = fmaf(av1, w1.y, acc[1][5]);
        acc[1][6] = fmaf(av1, w1.z, acc[1][6]);
        acc[1][7] = fmaf(av1, w1.w, acc[1][7]);
    }

    float gg[8], be[8];
#pragma unroll
    for (int j = 0; j < 8; j++) {
        gg[j] = gamma[og * 8 + j];
        be[j] = beta[og * 8 + j];
    }

#pragma unroll
    for (int n = 0; n < 2; n++) {
        int node = base + wid * 8 + ng + 4 * n;
        float h[8];
        if (node < n_nodes) {
            const float4* hp = (const float4*)(g_h1 + (size_t)node * DIM + og * 8);
            float4 h0 = hp[0], h1v = hp[1];
            h[0] = h0.x; h[1] = h0.y; h[2] = h0.z; h[3] = h0.w;
            h[4] = h1v.x; h[5] = h1v.y; h[6] = h1v.z; h[7] = h1v.w;
        } else {
#pragma unroll
            for (int j = 0; j < 8; j++) h[j] = 0.0f;
        }

        float s = 0.0f, s2 = 0.0f;
#pragma unroll
        for (int j = 0; j < 8; j++) {
            float v = fmaxf(h[j] + acc[n][j], 0.0f);
            h[j] = v;
            s += v;
            s2 = fmaf(v, v, s2);
        }
#pragma unroll
        for (int m = 4; m <= 16; m <<= 1) {
            s  += __shfl_xor_sync(0xFFFFFFFFu, s,  m);
            s2 += __shfl_xor_sync(0xFFFFFFFFu, s2, m);
        }
        float mu  = s * (1.0f / 64.0f);
        float var = s2 * (1.0f / 64.0f) - mu * mu;
        float rstd = rsqrtf(var + LN_EPS);

        if (node < n_nodes) {
            float4 v0, v1;
            v0.x = (h[0] - mu) * rstd * gg[0] + be[0];
            v0.y = (h[1] - mu) * rstd * gg[1] + be[1];
            v0.z = (h[2] - mu) * rstd * gg[2] + be[2];
            v0.w = (h[3] - mu) * rstd * gg[3] + be[3];
            v1.x = (h[4] - mu) * rstd * gg[4] + be[4];
            v1.y = (h[5] - mu) * rstd * gg[5] + be[5];
            v1.z = (h[6] - mu) * rstd * gg[6] + be[6];
            v1.w = (h[7] - mu) * rstd * gg[7] + be[7];
            float4* op = (float4*)(out + (size_t)node * DIM + og * 8);
            op[0] = v0;
            op[1] = v1;
        }
    }
}

// ---------------------------------------------------------------------------
extern "C" void kernel_launch(void* const* d_in, const int* in_sizes, int n_in,
                              void* d_out, int out_size) {
    const float* x     = (const float*)d_in[0];   // [N, 64]
    const float* W     = (const float*)d_in[1];   // [64, 128]
    const float* b     = (const float*)d_in[2];   // [64]
    const float* gamma = (const float*)d_in[3];   // [64]
    const float* beta  = (const float*)d_in[4];   // [64]
    const void*  ei    = d_in[5];                 // [2, E] int32 or int64

    int n_nodes = in_sizes[0] / DIM;
    int n_edges = in_sizes[5] / 2;
    float* out = (float*)d_out;

    int agg4 = n_nodes * (DIM / 4);
    int init_blocks = (agg4 + 255) / 256;
    init_kernel<<<init_blocks, 256>>>(W, (const unsigned*)ei, n_nodes);

    int nA = (n_nodes + NPB_A - 1) / NPB_A;                   // 3125
    int epb = (n_edges + nA - 1) / nA;                        // ~384
    if (epb < 1) epb = 1;
    phaseA_kernel<<<nA, 256, SMEM_A * sizeof(float)>>>(x, b, ei, n_nodes, n_edges, epb);

    int nB = (n_nodes + NPB_B - 1) / NPB_B;                   // 1563
    phaseB_kernel<<<nB, 256, SMEM_B * sizeof(float)>>>(gamma, beta, out, n_nodes);
}